// round 1
// baseline (speedup 1.0000x reference)
#include <cuda_runtime.h>
#include <cstdint>

#define NCTA     125
#define ROWS     16          // output rows per CTA: 125*16 = 2000
#define NTHREADS 256         // 8 warps
#define RDIM     2000
#define CEXT     2048        // 2000 h + 28 x + 20 zero pad
#define XDIM     28
#define TSTEPS   28
#define BATCH    512
#define NSTEP    (BATCH*TSTEPS)   // 14336 sequential steps
#define ODIM     10

// Scratch (static __device__ arrays; no allocation anywhere)
__device__ float    g_h[2][CEXT];        // double-buffered hidden state (+ zero tail)
__device__ float    g_hlast[BATCH*RDIM]; // h at t = T-1 per batch element
__device__ unsigned g_bar;               // monotonic grid barrier counter

// ---- packed f32x2 helpers (2x FFMA throughput; only reachable via PTX) ----
__device__ __forceinline__ unsigned long long fma2(unsigned long long a,
                                                   unsigned long long b,
                                                   unsigned long long c) {
    unsigned long long d;
    asm("fma.rn.f32x2 %0, %1, %2, %3;" : "=l"(d) : "l"(a), "l"(b), "l"(c));
    return d;
}
__device__ __forceinline__ unsigned long long mul2(unsigned long long a,
                                                   unsigned long long b) {
    unsigned long long d;
    asm("mul.rn.f32x2 %0, %1, %2;" : "=l"(d) : "l"(a), "l"(b));
    return d;
}
__device__ __forceinline__ unsigned long long pk2(float lo, float hi) {
    unsigned long long u;
    asm("mov.b64 %0, {%1, %2};" : "=l"(u)
        : "r"(__float_as_uint(lo)), "r"(__float_as_uint(hi)));
    return u;
}
__device__ __forceinline__ float lo32(unsigned long long v) { return __uint_as_float((unsigned)v); }
__device__ __forceinline__ float hi32(unsigned long long v) { return __uint_as_float((unsigned)(v >> 32)); }

// W_ext element: [W_res | W_in | 0-pad], row r, extended column c
__device__ __forceinline__ float wext(const float* __restrict__ Wres,
                                      const float* __restrict__ Win,
                                      int r, int c) {
    if (c < RDIM)        return Wres[r * RDIM + c];
    if (c < RDIM + XDIM) return Win[r * XDIM + (c - RDIM)];
    return 0.0f;
}

// Register reduce-scatter stage: 32 lanes, segment halving via shfl.xor.
template <int M, int HALF>
__device__ __forceinline__ void rs_stage(float* a, int l) {
    const bool up = (l & M) != 0;
#pragma unroll
    for (int i = 0; i < HALF; ++i) {
        float send = up ? a[i] : a[i + HALF];
        float recv = __shfl_xor_sync(0xffffffffu, send, M);
        a[i] = (up ? a[i + HALF] : a[i]) + recv;
    }
}

__global__ void reset_kernel() {
    const int t = blockIdx.x * blockDim.x + threadIdx.x;
    if (t == 0) g_bar = 0u;
    if (t < RDIM) g_h[1][t] = 0.0f;   // h0 = 0 (buffer read by step 0)
}

__global__ void __launch_bounds__(NTHREADS, 1)
rnn_kernel(const float* __restrict__ x,
           const float* __restrict__ W_in,
           const float* __restrict__ W_res) {
    __shared__ __align__(16) float sh[CEXT];
    __shared__ float spart[8 * ROWS];

    const int tid   = threadIdx.x;
    const int w     = tid >> 5;
    const int l     = tid & 31;
    const int rbase = blockIdx.x * ROWS;
    // Lane column base: warp stripe of 256 cols, two conflict-free float4 groups
    const int c0 = w * 256 + l * 4;

    // ---- Load W_ext slice into registers (persistent across all 14336 steps) ----
    unsigned long long W2[ROWS][4];
#pragma unroll
    for (int r = 0; r < ROWS; ++r) {
        const int gr = rbase + r;
#pragma unroll
        for (int q = 0; q < 4; ++q) {
            const int c = c0 + (q >> 1) * 128 + (q & 1) * 2;
            W2[r][q] = pk2(wext(W_res, W_in, gr, c),
                           wext(W_res, W_in, gr, c + 1));
        }
    }

    // Zero SMEM pad columns [2028, 2048) once (never overwritten in the loop)
    if (tid < 5) ((float4*)sh)[507 + tid] = make_float4(0.f, 0.f, 0.f, 0.f);

    for (int s = 0; s < NSTEP; ++s) {
        // ---- Wait for all CTAs to have published h_{s-1} ----
        if (tid == 0 && s > 0) {
            const unsigned target = (unsigned)s * NCTA;
            unsigned v;
            do {
                asm volatile("ld.acquire.gpu.u32 %0, [%1];"
                             : "=r"(v) : "l"(&g_bar) : "memory");
            } while (v < target);
        }
        __syncthreads();

        // ---- Stage h_{s-1} (L2, bypass L1) + x_t into SMEM ----
        const float4* hsrc = (const float4*)g_h[(s + 1) & 1];
        {
            float4 va = __ldcg(hsrc + tid);            // float4 idx 0..255
            ((float4*)sh)[tid] = va;
        }
        if (tid < 244) {                               // idx 256..499 (h ends at 499)
            float4 vb = __ldcg(hsrc + tid + 256);
            ((float4*)sh)[tid + 256] = vb;
        }
        if (tid < 7) {                                 // x_t: 28 floats = 7 float4
            ((float4*)sh)[500 + tid] =
                __ldg((const float4*)(x + (size_t)s * XDIM) + tid);
        }
        __syncthreads();

        // ---- Matvec: 16 rows x 8 cols per thread, packed f32x2 FMAs ----
        const ulonglong2 ha = *(const ulonglong2*)(sh + c0);
        const ulonglong2 hb = *(const ulonglong2*)(sh + c0 + 128);

        unsigned long long acc[ROWS];
#pragma unroll
        for (int r = 0; r < ROWS; ++r) acc[r] = mul2(W2[r][0], ha.x);
#pragma unroll
        for (int r = 0; r < ROWS; ++r) acc[r] = fma2(W2[r][1], ha.y, acc[r]);
#pragma unroll
        for (int r = 0; r < ROWS; ++r) acc[r] = fma2(W2[r][2], hb.x, acc[r]);
#pragma unroll
        for (int r = 0; r < ROWS; ++r) acc[r] = fma2(W2[r][3], hb.y, acc[r]);

        float a[ROWS];
#pragma unroll
        for (int r = 0; r < ROWS; ++r) a[r] = lo32(acc[r]) + hi32(acc[r]);

        // ---- Warp reduce-scatter: 16 rows across 32 lanes (16 shfl/lane) ----
        rs_stage<16, 8>(a, l);
        rs_stage<8, 4>(a, l);
        rs_stage<4, 2>(a, l);
        rs_stage<2, 1>(a, l);
        float v = a[0] + __shfl_xor_sync(0xffffffffu, a[0], 1);
        if ((l & 1) == 0) spart[w * ROWS + (l >> 1)] = v;
        __syncthreads();

        // ---- Cross-warp combine + tanh + publish ----
        if (tid < ROWS) {
            float sum = spart[tid];
#pragma unroll
            for (int ww = 1; ww < 8; ++ww) sum += spart[ww * ROWS + tid];
            const float hv = tanhf(sum);
            __stcg(&g_h[s & 1][rbase + tid], hv);
            if ((s % TSTEPS) == TSTEPS - 1)
                g_hlast[(s / TSTEPS) * RDIM + rbase + tid] = hv;
        }
        __syncthreads();
        if (tid == 0) {
            __threadfence();            // release before arrive
            atomicAdd(&g_bar, 1u);
        }
    }
}

__global__ void out_kernel(const float* __restrict__ W_out,
                           float* __restrict__ out) {
    const int b   = blockIdx.x;
    const int tid = threadIdx.x;
    const float* __restrict__ h = g_hlast + b * RDIM;

    float acc[ODIM];
#pragma unroll
    for (int o = 0; o < ODIM; ++o) acc[o] = 0.f;

    for (int k = tid; k < RDIM; k += 256) {
        const float hv = h[k];
#pragma unroll
        for (int o = 0; o < ODIM; ++o)
            acc[o] = fmaf(W_out[o * RDIM + k], hv, acc[o]);
    }
#pragma unroll
    for (int o = 0; o < ODIM; ++o) {
#pragma unroll
        for (int m = 16; m >= 1; m >>= 1)
            acc[o] += __shfl_xor_sync(0xffffffffu, acc[o], m);
    }
    __shared__ float sp[8][ODIM];
    if ((tid & 31) == 0) {
#pragma unroll
        for (int o = 0; o < ODIM; ++o) sp[tid >> 5][o] = acc[o];
    }
    __syncthreads();
    if (tid < ODIM) {
        float s2 = 0.f;
#pragma unroll
        for (int ww = 0; ww < 8; ++ww) s2 += sp[ww][tid];
        out[b * ODIM + tid] = s2;
    }
}

extern "C" void kernel_launch(void* const* d_in, const int* in_sizes, int n_in,
                              void* d_out, int out_size) {
    (void)in_sizes; (void)n_in; (void)out_size;
    const float* x     = (const float*)d_in[0];
    const float* W_in  = (const float*)d_in[1];
    const float* W_res = (const float*)d_in[2];
    const float* W_out = (const float*)d_in[3];
    float* out = (float*)d_out;

    reset_kernel<<<8, 256>>>();                 // zero barrier + h0 each launch
    rnn_kernel<<<NCTA, NTHREADS>>>(x, W_in, W_res);  // 125 CTAs <= 148 SMs, 1/SM
    out_kernel<<<BATCH, 256>>>(W_out, out);
}